// round 12
// baseline (speedup 1.0000x reference)
#include <cuda_runtime.h>
#include <cuda_bf16.h>
#include <cstdint>

#define NS    8192
#define NHALF 4096
#define D     256
#define TS    128          // output tile (M=N)
#define KC    128          // int8 K elems per smem stage (128 B rows)
#define NSTAGE (D / KC)    // 2
#define NTILE  64          // NS / TS
#define NBLK   (NTILE * (NTILE + 1) / 2)   // 2080 upper-triangle tiles
#define PREPB  512         // k_prep blocks (16 rows each)

// ---- device-global scratch (no allocs allowed) ------------------------------
__device__ double g_acc;
__device__ float  g_colpart[PREPB * D];      // per-block column-sum partials
__device__ float  g_sqpart[PREPB];           // per-block sum-of-norms partials
__device__ float  g_sq[NS];                  // exact fp32 row norms
__device__ float  g_sc[NS];                  // per-row quant scale s_i = max/127
__device__ float  g_C;                       // log2(e) / (16*b)
__device__ unsigned g_pctr = 0;              // k_prep completion counter
__device__ unsigned g_mctr = 0;              // k_mmd completion counter
__device__ __align__(16) int8_t g_Y[(size_t)NS * D];   // 2 MB quantized rows

// ---- helpers ----------------------------------------------------------------
__device__ __forceinline__ float ex2f_fast(float x) {
    float y; asm("ex2.approx.f32 %0, %1;" : "=f"(y) : "f"(x)); return y;
}
__device__ __forceinline__ uint32_t smem_u32(const void* p) {
    uint32_t a;
    asm("{ .reg .u64 t; cvta.to.shared.u64 t, %1; cvt.u32.u64 %0, t; }" : "=r"(a) : "l"(p));
    return a;
}
__device__ __forceinline__ void cp16(uint32_t dst, const void* src) {
    asm volatile("cp.async.cg.shared.global [%0], [%1], 16;" :: "r"(dst), "l"(src));
}
#define CP_COMMIT() asm volatile("cp.async.commit_group;" ::: "memory")
#define CP_WAIT(n)  asm volatile("cp.async.wait_group %0;" :: "n"(n) : "memory")

__device__ __forceinline__ void ldm4(uint32_t* r, uint32_t a) {
    asm volatile("ldmatrix.sync.aligned.m8n8.x4.shared.b16 {%0,%1,%2,%3}, [%4];"
        : "=r"(r[0]), "=r"(r[1]), "=r"(r[2]), "=r"(r[3]) : "r"(a));
}
// s8 IMMA m16n8k32, s32 accumulate
__device__ __forceinline__ void imma16832(int* c, const uint32_t* a, const uint32_t* b) {
    asm volatile("mma.sync.aligned.m16n8k32.row.col.s32.s8.s8.s32 "
        "{%0,%1,%2,%3}, {%4,%5,%6,%7}, {%8,%9}, {%0,%1,%2,%3};"
        : "+r"(c[0]), "+r"(c[1]), "+r"(c[2]), "+r"(c[3])
        : "r"(a[0]), "r"(a[1]), "r"(a[2]), "r"(a[3]), "r"(b[0]), "r"(b[1]));
}

// SW128-style XOR swizzle for tiles with 128-byte rows (cp path only).
__device__ __forceinline__ uint32_t swz(uint32_t off) {
    return off ^ ((off >> 3) & 0x70);
}

__device__ __forceinline__ const float* row_ptr(const float* __restrict__ s,
                                                const float* __restrict__ t, int i) {
    return (i < NHALF) ? (s + (size_t)i * D) : (t + (size_t)(i - NHALF) * D);
}

// ---------------------------------------------------------------------------
// Fused prep: per-row L2 norm (exact fp32), per-row int8 quantization,
// per-block column-sum/norm-sum partials; last block computes bandwidth g_C.
__global__ __launch_bounds__(256) void k_prep(const float* __restrict__ s,
                                              const float* __restrict__ t) {
    __shared__ float colp[8][256];
    __shared__ float wsum[8];
    __shared__ unsigned s_done;
    int warp = threadIdx.x >> 5, lane = threadIdx.x & 31;

    float4 ca = make_float4(0.f, 0.f, 0.f, 0.f);
    float4 cb = make_float4(0.f, 0.f, 0.f, 0.f);
    float normsum = 0.0f;

    #pragma unroll
    for (int r = 0; r < 2; ++r) {
        int row = blockIdx.x * 16 + warp * 2 + r;
        const float4* p = (const float4*)row_ptr(s, t, row);
        float4 a = p[lane];          // cols 4*lane .. 4*lane+3
        float4 b = p[lane + 32];     // cols 128+4*lane ..

        float v = a.x * a.x + a.y * a.y + a.z * a.z + a.w * a.w
                + b.x * b.x + b.y * b.y + b.z * b.z + b.w * b.w;
        float m = fmaxf(fmaxf(fmaxf(fabsf(a.x), fabsf(a.y)), fmaxf(fabsf(a.z), fabsf(a.w))),
                        fmaxf(fmaxf(fabsf(b.x), fabsf(b.y)), fmaxf(fabsf(b.z), fabsf(b.w))));
        #pragma unroll
        for (int o = 16; o; o >>= 1) {
            v += __shfl_xor_sync(0xffffffffu, v, o);
            m  = fmaxf(m, __shfl_xor_sync(0xffffffffu, m, o));
        }
        if (lane == 0) {
            g_sq[row] = v;
            g_sc[row] = m * (1.0f / 127.0f);
            normsum += v;
        }

        // quantize: q = round(x * 127/m), pack 4 x s8 per u32
        float inv = (m > 0.0f) ? (127.0f / m) : 0.0f;
        int qa0 = __float2int_rn(a.x * inv), qa1 = __float2int_rn(a.y * inv);
        int qa2 = __float2int_rn(a.z * inv), qa3 = __float2int_rn(a.w * inv);
        int qb0 = __float2int_rn(b.x * inv), qb1 = __float2int_rn(b.y * inv);
        int qb2 = __float2int_rn(b.z * inv), qb3 = __float2int_rn(b.w * inv);
        uint32_t ua = (uint32_t)(qa0 & 0xFF) | ((uint32_t)(qa1 & 0xFF) << 8)
                    | ((uint32_t)(qa2 & 0xFF) << 16) | ((uint32_t)qa3 << 24);
        uint32_t ub = (uint32_t)(qb0 & 0xFF) | ((uint32_t)(qb1 & 0xFF) << 8)
                    | ((uint32_t)(qb2 & 0xFF) << 16) | ((uint32_t)qb3 << 24);
        uint32_t* yrow = (uint32_t*)(g_Y + (size_t)row * D);
        yrow[lane]      = ua;
        yrow[lane + 32] = ub;

        ca.x += a.x; ca.y += a.y; ca.z += a.z; ca.w += a.w;
        cb.x += b.x; cb.y += b.y; cb.z += b.z; cb.w += b.w;
    }

    ((float4*)colp[warp])[lane]      = ca;
    ((float4*)colp[warp])[lane + 32] = cb;
    if (lane == 0) wsum[warp] = normsum;
    __syncthreads();

    int tid = threadIdx.x;           // 0..255 = column index
    float cs = 0.0f;
    #pragma unroll
    for (int w = 0; w < 8; ++w) cs += colp[w][tid];
    g_colpart[blockIdx.x * D + tid] = cs;
    if (tid == 0) {
        float ss = 0.0f;
        #pragma unroll
        for (int w = 0; w < 8; ++w) ss += wsum[w];
        g_sqpart[blockIdx.x] = ss;
        g_acc = 0.0;
    }

    // last-block bandwidth computation
    __threadfence();
    if (tid == 0) s_done = atomicAdd(&g_pctr, 1u);
    __syncthreads();
    if (s_done == PREPB - 1) {
        __shared__ float red[256];
        float c2 = 0.0f;
        #pragma unroll 8
        for (int b = 0; b < PREPB; ++b) c2 += g_colpart[b * D + tid];
        red[tid] = c2 * c2;
        __syncthreads();
        for (int o = 128; o; o >>= 1) { if (tid < o) red[tid] += red[tid + o]; __syncthreads(); }
        float csq = red[0];
        __syncthreads();
        float sp = 0.0f;
        #pragma unroll
        for (int b = tid; b < PREPB; b += 256) sp += g_sqpart[b];
        red[tid] = sp;
        __syncthreads();
        for (int o = 128; o; o >>= 1) { if (tid < o) red[tid] += red[tid + o]; __syncthreads(); }
        if (tid == 0) {
            double suml2 = 2.0 * (double)NS * (double)red[0] - 2.0 * (double)csq;
            double bw = suml2 / ((double)NS * (double)NS - (double)NS);
            double b = bw / 4.0;     // KERNEL_MUL^(KERNEL_NUM//2) = 2^2
            g_C = (float)(1.4426950408889634 / (16.0 * b));
            g_pctr = 0;              // reset for next graph replay
        }
    }
}

// ---------------------------------------------------------------------------
// INT8 warp-IMMA fused Gram + Gaussian epilogue. 2080 CTAs, 8 warps each,
// 64x32 warp tiles over 128x128 (small per-thread state -> 16 warps/SM at
// 2 CTAs/SM = 4 warps/SMSP for latency hiding). K=256 int8 in 2 stages of
// 128 (128B rows), cp.async double-buffered, single-buffered fragments.
#define STAGE_BYTES 32768                    // A(16KB) + B(16KB)
#define SMEM_TOTAL  (2 * STAGE_BYTES)        // 64KB dyn; 2 CTAs/SM

__global__ __launch_bounds__(256, 2) void k_mmd(float* __restrict__ out) {
    // linear bid -> (ib, jb), jb >= ib.
    int bid = blockIdx.x;
    int ib = (int)(64.5f - sqrtf(64.5f * 64.5f - 2.0f * (float)bid));
    #pragma unroll 1
    while ((64 * (ib + 1) - ((ib + 1) * ib) / 2) <= bid) ++ib;
    #pragma unroll 1
    while ((64 * ib - (ib * (ib - 1)) / 2) > bid) --ib;
    int jb = ib + (bid - (64 * ib - (ib * (ib - 1)) / 2));

    extern __shared__ char sm[];
    __shared__ float s_nCi[128], s_nCj[128], s_sci[128], s_scj[128], s_red[256];
    uint32_t sbase = smem_u32(sm);

    int tid  = threadIdx.x;
    int warp = tid >> 5, lane = tid & 31;
    int wm = warp >> 2, wn = warp & 3;        // warp tile: rows wm*64, cols wn*32
    int rI = ib * TS, rJ = jb * TS;

    float C = g_C;
    float twoC = 2.0f * C;
    if (tid < 128) {
        s_nCi[tid] = -C * g_sq[rI + tid];
        s_sci[tid] = twoC * g_sc[rI + tid];   // pre-scaled row quant scale
    } else {
        int u = tid - 128;
        s_nCj[u] = -C * g_sq[rJ + u];
        s_scj[u] = g_sc[rJ + u];
    }

    const int8_t* YA = g_Y + (size_t)rI * D;
    const int8_t* YB = g_Y + (size_t)rJ * D;

    // hoisted LDSM addressing: swz(row*128+kb) == row*128 + (kb ^ ((lane&7)<<4))
    int lane15 = lane & 15;
    uint32_t xr  = (uint32_t)((lane & 7) << 4);
    uint32_t kb0 = (uint32_t)((lane >> 4) * 16);
    uint32_t ra[4], rb[2];
    #pragma unroll
    for (int i = 0; i < 4; ++i)
        ra[i] = (uint32_t)((wm * 64 + i * 16 + lane15) * 128);
    #pragma unroll
    for (int j2 = 0; j2 < 2; ++j2)
        rb[j2] = (uint32_t)((wn * 32 + j2 * 16 + lane15) * 128);

    auto issue_stage = [&](int st, int buf) {
        int k0 = st * KC;                      // byte offset within 256B row
        uint32_t base = sbase + buf * STAGE_BYTES;
        #pragma unroll
        for (int t = 0; t < 4; ++t) {
            int chunk = tid + t * 256;           // 0..1023
            int r = chunk >> 3, c16 = chunk & 7;
            uint32_t d = swz((uint32_t)(r * 128 + c16 * 16));
            cp16(base + d,         YA + (size_t)r * D + k0 + c16 * 16);
            cp16(base + 16384 + d, YB + (size_t)r * D + k0 + c16 * 16);
        }
        CP_COMMIT();
    };

    int acc[4][4][4] = {};

    issue_stage(0, 0);
    issue_stage(1, 1);

    #pragma unroll
    for (int st = 0; st < NSTAGE; ++st) {
        if (st == 0) CP_WAIT(1);
        else         CP_WAIT(0);
        __syncthreads();

        uint32_t Ab = sbase + st * STAGE_BYTES;
        uint32_t Bb = Ab + 16384;

        #pragma unroll
        for (int kk = 0; kk < 4; ++kk) {       // 4 k-steps of k=32 per stage
            uint32_t koff = ((uint32_t)(kk << 5) | kb0) ^ xr;
            uint32_t afr[4][4], bfr[4][2];
            #pragma unroll
            for (int i = 0; i < 4; ++i)
                ldm4(afr[i], Ab + ra[i] + koff);
            #pragma unroll
            for (int j2 = 0; j2 < 2; ++j2) {
                uint32_t q[4];
                ldm4(q, Bb + rb[j2] + koff);
                bfr[j2 * 2 + 0][0] = q[0]; bfr[j2 * 2 + 0][1] = q[2];
                bfr[j2 * 2 + 1][0] = q[1]; bfr[j2 * 2 + 1][1] = q[3];
            }
            #pragma unroll
            for (int i = 0; i < 4; ++i)
                #pragma unroll
                for (int j = 0; j < 4; ++j)
                    imma16832(acc[i][j], afr[i], bfr[j]);
        }
        __syncthreads();
    }

    // ---- fused epilogue: arg = fma(2C*s_i*s_j, acc, nCi+nCj) ----
    float partial = 0.0f;
    #pragma unroll
    for (int i = 0; i < 4; ++i) {
        int r_lo = wm * 64 + i * 16 + (lane >> 2);
        float ni_lo = s_nCi[r_lo], ni_hi = s_nCi[r_lo + 8];
        float si_lo = s_sci[r_lo], si_hi = s_sci[r_lo + 8];
        #pragma unroll
        for (int j = 0; j < 4; ++j) {
            int c_lo = wn * 32 + j * 8 + (lane & 3) * 2;
            float nj0 = s_nCj[c_lo], nj1 = s_nCj[c_lo + 1];
            float sj0 = s_scj[c_lo], sj1 = s_scj[c_lo + 1];
            float ua = ex2f_fast(fmaf(si_lo * sj0, (float)acc[i][j][0], ni_lo + nj0));
            float ub = ex2f_fast(fmaf(si_lo * sj1, (float)acc[i][j][1], ni_lo + nj1));
            float uc = ex2f_fast(fmaf(si_hi * sj0, (float)acc[i][j][2], ni_hi + nj0));
            float ud = ex2f_fast(fmaf(si_hi * sj1, (float)acc[i][j][3], ni_hi + nj1));
            #pragma unroll
            for (int e = 0; e < 4; ++e) {
                float u = (e == 0) ? ua : (e == 1) ? ub : (e == 2) ? uc : ud;
                float u2 = u * u;
                float u4 = u2 * u2;
                float u8 = u4 * u4;
                float hi = fmaf(u8, u8, u8);        // u16 + u8
                partial += (u + u2) + (u4 + hi);
            }
        }
    }
    float sgn = ((ib < 32) == (jb < 32)) ? 1.0f : -1.0f;
    partial *= (ib == jb) ? sgn : 2.0f * sgn;

    s_red[tid] = partial;
    __syncthreads();
    for (int o = 128; o >= 32; o >>= 1) {
        if (tid < o) s_red[tid] += s_red[tid + o];
        __syncthreads();
    }
    if (tid < 32) {
        float v = s_red[tid];
        #pragma unroll
        for (int o = 16; o; o >>= 1) v += __shfl_down_sync(0xffffffffu, v, o);
        if (tid == 0) atomicAdd(&g_acc, (double)v);
    }

    // last CTA writes the result
    if (tid == 0) {
        __threadfence();
        unsigned d = atomicAdd(&g_mctr, 1u);
        if (d == NBLK - 1) {
            out[0] = (float)(g_acc / ((double)NHALF * (double)NHALF));
            g_mctr = 0;      // reset for next graph replay
        }
    }
}

// ---------------------------------------------------------------------------
extern "C" void kernel_launch(void* const* d_in, const int* in_sizes, int n_in,
                              void* d_out, int out_size) {
    const float* s = (const float*)d_in[0];
    const float* t = (const float*)d_in[1];
    float* out = (float*)d_out;

    cudaFuncSetAttribute(k_mmd, cudaFuncAttributeMaxDynamicSharedMemorySize, SMEM_TOTAL);

    k_prep<<<PREPB, 256>>>(s, t);
    k_mmd<<<NBLK, 256, SMEM_TOTAL>>>(out);
}

// round 13
// speedup vs baseline: 1.2368x; 1.2368x over previous
#include <cuda_runtime.h>
#include <cuda_bf16.h>
#include <cstdint>

#define NS    8192
#define NHALF 4096
#define D     256
#define TS    128          // output tile (M=N)
#define KC    128          // int8 K elems per smem stage (128 B rows)
#define NSTAGE (D / KC)    // 2
#define NTILE  64          // NS / TS
#define NBLK   (NTILE * (NTILE + 1) / 2)   // 2080 upper-triangle tiles
#define PREPB  256         // k_prep blocks (32 rows each)

// ---- device-global scratch (no allocs allowed) ------------------------------
__device__ double g_acc;
__device__ float  g_colpart[PREPB * D];      // per-block column-sum partials
__device__ float  g_sqpart[PREPB];           // per-block sum-of-norms partials
__device__ float  g_sq[NS];                  // exact fp32 row norms
__device__ float  g_sc[NS];                  // per-row quant scale s_i = max/127
__device__ float  g_C;                       // log2(e) / (16*b)
__device__ unsigned g_pctr = 0;              // k_prep completion counter
__device__ unsigned g_mctr = 0;              // k_mmd completion counter
__device__ __align__(16) int8_t g_Y[(size_t)NS * D];   // 2 MB quantized rows

// ---- helpers ----------------------------------------------------------------
__device__ __forceinline__ float ex2f_fast(float x) {
    float y; asm("ex2.approx.f32 %0, %1;" : "=f"(y) : "f"(x)); return y;
}
__device__ __forceinline__ uint32_t smem_u32(const void* p) {
    uint32_t a;
    asm("{ .reg .u64 t; cvta.to.shared.u64 t, %1; cvt.u32.u64 %0, t; }" : "=r"(a) : "l"(p));
    return a;
}
__device__ __forceinline__ void cp16(uint32_t dst, const void* src) {
    asm volatile("cp.async.cg.shared.global [%0], [%1], 16;" :: "r"(dst), "l"(src));
}
#define CP_COMMIT() asm volatile("cp.async.commit_group;" ::: "memory")
#define CP_WAIT(n)  asm volatile("cp.async.wait_group %0;" :: "n"(n) : "memory")

__device__ __forceinline__ void ldm4(uint32_t* r, uint32_t a) {
    asm volatile("ldmatrix.sync.aligned.m8n8.x4.shared.b16 {%0,%1,%2,%3}, [%4];"
        : "=r"(r[0]), "=r"(r[1]), "=r"(r[2]), "=r"(r[3]) : "r"(a));
}
// s8 IMMA m16n8k32, s32 accumulate
__device__ __forceinline__ void imma16832(int* c, const uint32_t* a, const uint32_t* b) {
    asm volatile("mma.sync.aligned.m16n8k32.row.col.s32.s8.s8.s32 "
        "{%0,%1,%2,%3}, {%4,%5,%6,%7}, {%8,%9}, {%0,%1,%2,%3};"
        : "+r"(c[0]), "+r"(c[1]), "+r"(c[2]), "+r"(c[3])
        : "r"(a[0]), "r"(a[1]), "r"(a[2]), "r"(a[3]), "r"(b[0]), "r"(b[1]));
}

// ---- packed f32x2 (Blackwell FFMA2/FADD2 pipe) ------------------------------
__device__ __forceinline__ uint64_t pk2(float lo, float hi) {
    uint64_t r; asm("mov.b64 %0, {%1, %2};" : "=l"(r) : "f"(lo), "f"(hi)); return r;
}
__device__ __forceinline__ void unpk2(float& lo, float& hi, uint64_t v) {
    asm("mov.b64 {%0, %1}, %2;" : "=f"(lo), "=f"(hi) : "l"(v));
}
__device__ __forceinline__ uint64_t mul2(uint64_t a, uint64_t b) {
    uint64_t r; asm("mul.rn.f32x2 %0, %1, %2;" : "=l"(r) : "l"(a), "l"(b)); return r;
}
__device__ __forceinline__ uint64_t add2(uint64_t a, uint64_t b) {
    uint64_t r; asm("add.rn.f32x2 %0, %1, %2;" : "=l"(r) : "l"(a), "l"(b)); return r;
}
__device__ __forceinline__ uint64_t fma2(uint64_t a, uint64_t b, uint64_t c) {
    uint64_t r; asm("fma.rn.f32x2 %0, %1, %2, %3;" : "=l"(r) : "l"(a), "l"(b), "l"(c)); return r;
}

// SW128-style XOR swizzle for tiles with 128-byte rows (cp path only).
__device__ __forceinline__ uint32_t swz(uint32_t off) {
    return off ^ ((off >> 3) & 0x70);
}

__device__ __forceinline__ const float* row_ptr(const float* __restrict__ s,
                                                const float* __restrict__ t, int i) {
    return (i < NHALF) ? (s + (size_t)i * D) : (t + (size_t)(i - NHALF) * D);
}

// ---------------------------------------------------------------------------
// Fused prep: per-row L2 norm (exact fp32), per-row int8 quantization,
// per-block column-sum/norm-sum partials; last block computes bandwidth g_C.
__global__ __launch_bounds__(256) void k_prep(const float* __restrict__ s,
                                              const float* __restrict__ t) {
    __shared__ float colp[8][256];
    __shared__ float wsum[8];
    __shared__ unsigned s_done;
    int warp = threadIdx.x >> 5, lane = threadIdx.x & 31;

    float4 ca = make_float4(0.f, 0.f, 0.f, 0.f);
    float4 cb = make_float4(0.f, 0.f, 0.f, 0.f);
    float normsum = 0.0f;

    #pragma unroll
    for (int r = 0; r < 4; ++r) {
        int row = blockIdx.x * 32 + warp * 4 + r;
        const float4* p = (const float4*)row_ptr(s, t, row);
        float4 a = p[lane];          // cols 4*lane .. 4*lane+3
        float4 b = p[lane + 32];     // cols 128+4*lane ..

        float v = a.x * a.x + a.y * a.y + a.z * a.z + a.w * a.w
                + b.x * b.x + b.y * b.y + b.z * b.z + b.w * b.w;
        float m = fmaxf(fmaxf(fmaxf(fabsf(a.x), fabsf(a.y)), fmaxf(fabsf(a.z), fabsf(a.w))),
                        fmaxf(fmaxf(fabsf(b.x), fabsf(b.y)), fmaxf(fabsf(b.z), fabsf(b.w))));
        #pragma unroll
        for (int o = 16; o; o >>= 1) {
            v += __shfl_xor_sync(0xffffffffu, v, o);
            m  = fmaxf(m, __shfl_xor_sync(0xffffffffu, m, o));
        }
        if (lane == 0) {
            g_sq[row] = v;
            g_sc[row] = m * (1.0f / 127.0f);
            normsum += v;
        }

        // quantize: q = round(x * 127/m), pack 4 x s8 per u32
        float inv = (m > 0.0f) ? (127.0f / m) : 0.0f;
        int qa0 = __float2int_rn(a.x * inv), qa1 = __float2int_rn(a.y * inv);
        int qa2 = __float2int_rn(a.z * inv), qa3 = __float2int_rn(a.w * inv);
        int qb0 = __float2int_rn(b.x * inv), qb1 = __float2int_rn(b.y * inv);
        int qb2 = __float2int_rn(b.z * inv), qb3 = __float2int_rn(b.w * inv);
        uint32_t ua = (uint32_t)(qa0 & 0xFF) | ((uint32_t)(qa1 & 0xFF) << 8)
                    | ((uint32_t)(qa2 & 0xFF) << 16) | ((uint32_t)qa3 << 24);
        uint32_t ub = (uint32_t)(qb0 & 0xFF) | ((uint32_t)(qb1 & 0xFF) << 8)
                    | ((uint32_t)(qb2 & 0xFF) << 16) | ((uint32_t)qb3 << 24);
        uint32_t* yrow = (uint32_t*)(g_Y + (size_t)row * D);
        yrow[lane]      = ua;
        yrow[lane + 32] = ub;

        ca.x += a.x; ca.y += a.y; ca.z += a.z; ca.w += a.w;
        cb.x += b.x; cb.y += b.y; cb.z += b.z; cb.w += b.w;
    }

    ((float4*)colp[warp])[lane]      = ca;
    ((float4*)colp[warp])[lane + 32] = cb;
    if (lane == 0) wsum[warp] = normsum;
    __syncthreads();

    int tid = threadIdx.x;           // 0..255 = column index
    float cs = 0.0f;
    #pragma unroll
    for (int w = 0; w < 8; ++w) cs += colp[w][tid];
    g_colpart[blockIdx.x * D + tid] = cs;
    if (tid == 0) {
        float ss = 0.0f;
        #pragma unroll
        for (int w = 0; w < 8; ++w) ss += wsum[w];
        g_sqpart[blockIdx.x] = ss;
        g_acc = 0.0;
    }

    // last-block bandwidth computation
    __threadfence();
    if (tid == 0) s_done = atomicAdd(&g_pctr, 1u);
    __syncthreads();
    if (s_done == PREPB - 1) {
        __shared__ float red[256];
        float c2 = 0.0f;
        #pragma unroll 8
        for (int b = 0; b < PREPB; ++b) c2 += g_colpart[b * D + tid];
        red[tid] = c2 * c2;
        __syncthreads();
        for (int o = 128; o; o >>= 1) { if (tid < o) red[tid] += red[tid + o]; __syncthreads(); }
        float csq = red[0];
        __syncthreads();
        red[tid] = g_sqpart[tid];        // PREPB == 256
        __syncthreads();
        for (int o = 128; o; o >>= 1) { if (tid < o) red[tid] += red[tid + o]; __syncthreads(); }
        if (tid == 0) {
            double suml2 = 2.0 * (double)NS * (double)red[0] - 2.0 * (double)csq;
            double bw = suml2 / ((double)NS * (double)NS - (double)NS);
            double b = bw / 4.0;     // KERNEL_MUL^(KERNEL_NUM//2) = 2^2
            g_C = (float)(1.4426950408889634 / (16.0 * b));
            g_pctr = 0;              // reset for next graph replay
        }
    }
}

// ---------------------------------------------------------------------------
// INT8 warp-IMMA fused Gram + Gaussian epilogue. 2080 CTAs, 4 warps each,
// 64x64 warp tiles over 128x128. K=256 int8 in 2 stages of 128 (128B rows),
// cp.async double-buffered, register double-buffered fragments, s8 IMMA k32.
// 3 CTAs/SM (12 warps, 3/SMSP); packed f32x2 power-sum epilogue.
#define STAGE_BYTES 32768                    // A(16KB) + B(16KB)
#define SMEM_TOTAL  (2 * STAGE_BYTES)        // 64KB dyn; 3 CTAs/SM ~ 200KB

__device__ __forceinline__ void load_frags(uint32_t Ab, uint32_t Bb, uint32_t koff,
                                           const uint32_t* ra, const uint32_t* rb,
                                           uint32_t afr[4][4], uint32_t bfr[8][2]) {
    #pragma unroll
    for (int i = 0; i < 4; ++i)
        ldm4(afr[i], Ab + ra[i] + koff);
    #pragma unroll
    for (int j2 = 0; j2 < 4; ++j2) {
        uint32_t q[4];
        ldm4(q, Bb + rb[j2] + koff);
        bfr[j2 * 2 + 0][0] = q[0]; bfr[j2 * 2 + 0][1] = q[2];
        bfr[j2 * 2 + 1][0] = q[1]; bfr[j2 * 2 + 1][1] = q[3];
    }
}

__global__ __launch_bounds__(128, 3) void k_mmd(float* __restrict__ out) {
    // linear bid -> (ib, jb), jb >= ib.
    int bid = blockIdx.x;
    int ib = (int)(64.5f - sqrtf(64.5f * 64.5f - 2.0f * (float)bid));
    #pragma unroll 1
    while ((64 * (ib + 1) - ((ib + 1) * ib) / 2) <= bid) ++ib;
    #pragma unroll 1
    while ((64 * ib - (ib * (ib - 1)) / 2) > bid) --ib;
    int jb = ib + (bid - (64 * ib - (ib * (ib - 1)) / 2));

    extern __shared__ char sm[];
    __shared__ float s_nCi[128], s_nCj[128], s_sci[128], s_scj[128], s_red[128];
    uint32_t sbase = smem_u32(sm);

    int tid  = threadIdx.x;
    int warp = tid >> 5, lane = tid & 31;
    int wm = warp >> 1, wn = warp & 1;        // warp tile: rows wm*64, cols wn*64
    int rI = ib * TS, rJ = jb * TS;

    float C = g_C;
    float twoC = 2.0f * C;
    s_nCi[tid] = -C * g_sq[rI + tid];
    s_nCj[tid] = -C * g_sq[rJ + tid];
    s_sci[tid] = twoC * g_sc[rI + tid];       // pre-scaled row quant scale
    s_scj[tid] = g_sc[rJ + tid];

    const int8_t* YA = g_Y + (size_t)rI * D;
    const int8_t* YB = g_Y + (size_t)rJ * D;

    // hoisted LDSM addressing: swz(row*128+kb) == row*128 + (kb ^ ((lane&7)<<4))
    int lane15 = lane & 15;
    uint32_t xr  = (uint32_t)((lane & 7) << 4);
    uint32_t kb0 = (uint32_t)((lane >> 4) * 16);
    uint32_t ra[4], rb[4];
    #pragma unroll
    for (int i = 0; i < 4; ++i) {
        ra[i] = (uint32_t)((wm * 64 + i * 16 + lane15) * 128);
        rb[i] = (uint32_t)((wn * 64 + i * 16 + lane15) * 128);
    }

    auto issue_stage = [&](int st, int buf) {
        int k0 = st * KC;                      // byte offset within 256B row
        uint32_t base = sbase + buf * STAGE_BYTES;
        #pragma unroll
        for (int t = 0; t < 8; ++t) {
            int chunk = tid + t * 128;           // 0..1023
            int r = chunk >> 3, c16 = chunk & 7;
            uint32_t d = swz((uint32_t)(r * 128 + c16 * 16));
            cp16(base + d,         YA + (size_t)r * D + k0 + c16 * 16);
            cp16(base + 16384 + d, YB + (size_t)r * D + k0 + c16 * 16);
        }
        CP_COMMIT();
    };

    int acc[4][8][4] = {};
    uint32_t afr[2][4][4], bfr[2][8][2];

    issue_stage(0, 0);
    issue_stage(1, 1);

    #pragma unroll
    for (int st = 0; st < NSTAGE; ++st) {
        if (st == 0) CP_WAIT(1);
        else         CP_WAIT(0);
        __syncthreads();

        uint32_t Ab = sbase + st * STAGE_BYTES;
        uint32_t Bb = Ab + 16384;

        load_frags(Ab, Bb, kb0 ^ xr, ra, rb, afr[0], bfr[0]);
        #pragma unroll
        for (int kk = 0; kk < 4; ++kk) {       // 4 k-steps of k=32 per stage
            int cur = kk & 1;
            if (kk < 3) {
                uint32_t koff = ((uint32_t)((kk + 1) << 5) | kb0) ^ xr;
                load_frags(Ab, Bb, koff, ra, rb, afr[cur ^ 1], bfr[cur ^ 1]);
            }
            #pragma unroll
            for (int i = 0; i < 4; ++i)
                #pragma unroll
                for (int j = 0; j < 8; ++j)
                    imma16832(acc[i][j], afr[cur][i], bfr[cur][j]);
        }
        __syncthreads();
    }

    // ---- fused epilogue: arg = fma(2C*s_i*s_j, acc, nCi+nCj); packed f32x2
    // power sum  u + u^2 + u^4 + u^8 + u^16  on pairs of elements.
    uint64_t part2 = pk2(0.0f, 0.0f);
    #pragma unroll
    for (int i = 0; i < 4; ++i) {
        int r_lo = wm * 64 + i * 16 + (lane >> 2);
        float ni_lo = s_nCi[r_lo], ni_hi = s_nCi[r_lo + 8];
        float si_lo = s_sci[r_lo], si_hi = s_sci[r_lo + 8];
        #pragma unroll
        for (int j = 0; j < 8; ++j) {
            int c_lo = wn * 64 + j * 8 + (lane & 3) * 2;
            float nj0 = s_nCj[c_lo], nj1 = s_nCj[c_lo + 1];
            float sj0 = s_scj[c_lo], sj1 = s_scj[c_lo + 1];
            float ua = ex2f_fast(fmaf(si_lo * sj0, (float)acc[i][j][0], ni_lo + nj0));
            float ub = ex2f_fast(fmaf(si_lo * sj1, (float)acc[i][j][1], ni_lo + nj1));
            float uc = ex2f_fast(fmaf(si_hi * sj0, (float)acc[i][j][2], ni_hi + nj0));
            float ud = ex2f_fast(fmaf(si_hi * sj1, (float)acc[i][j][3], ni_hi + nj1));
            uint64_t u_ab = pk2(ua, ub);
            uint64_t u_cd = pk2(uc, ud);
            #pragma unroll
            for (int e = 0; e < 2; ++e) {
                uint64_t u = (e == 0) ? u_ab : u_cd;
                uint64_t u2 = mul2(u, u);
                uint64_t u4 = mul2(u2, u2);
                uint64_t u8 = mul2(u4, u4);
                uint64_t hi = fma2(u8, u8, u8);           // u16 + u8
                part2 = add2(part2, add2(add2(u, u2), add2(u4, hi)));
            }
        }
    }
    float plo, phi;
    unpk2(plo, phi, part2);
    float partial = plo + phi;
    float sgn = ((ib < 32) == (jb < 32)) ? 1.0f : -1.0f;
    partial *= (ib == jb) ? sgn : 2.0f * sgn;

    s_red[tid] = partial;
    __syncthreads();
    if (tid < 64) s_red[tid] += s_red[tid + 64];
    __syncthreads();
    if (tid < 32) {
        float v = s_red[tid] + s_red[tid + 32];
        #pragma unroll
        for (int o = 16; o; o >>= 1) v += __shfl_down_sync(0xffffffffu, v, o);
        if (tid == 0) atomicAdd(&g_acc, (double)v);
    }

    // last CTA writes the result
    if (tid == 0) {
        __threadfence();
        unsigned d = atomicAdd(&g_mctr, 1u);
        if (d == NBLK - 1) {
            out[0] = (float)(g_acc / ((double)NHALF * (double)NHALF));
            g_mctr = 0;      // reset for next graph replay
        }
    }
}

// ---------------------------------------------------------------------------
extern "C" void kernel_launch(void* const* d_in, const int* in_sizes, int n_in,
                              void* d_out, int out_size) {
    const float* s = (const float*)d_in[0];
    const float* t = (const float*)d_in[1];
    float* out = (float*)d_out;

    cudaFuncSetAttribute(k_mmd, cudaFuncAttributeMaxDynamicSharedMemorySize, SMEM_TOTAL);

    k_prep<<<PREPB, 256>>>(s, t);
    k_mmd<<<NBLK, 128, SMEM_TOTAL>>>(out);
}